// round 9
// baseline (speedup 1.0000x reference)
#include <cuda_runtime.h>

#define SEQ   1024
#define BATCH 512
#define NC    48
#define FULL  0xffffffffu

__device__ int g_perm[BATCH];   // rank r -> batch index (descending length)

// ---- packed f32x2 helpers (sm_103a) ------------------------------------
static __device__ __forceinline__ unsigned long long pk2(float lo, float hi) {
    unsigned long long r;
    asm("mov.b64 %0, {%1,%2};" : "=l"(r) : "f"(lo), "f"(hi));
    return r;
}
static __device__ __forceinline__ unsigned long long fma2(
    unsigned long long a, unsigned long long b, unsigned long long c) {
    unsigned long long d;
    asm("fma.rn.f32x2 %0, %1, %2, %3;" : "=l"(d) : "l"(a), "l"(b), "l"(c));
    return d;
}
static __device__ __forceinline__ unsigned long long add2(
    unsigned long long a, unsigned long long b) {
    unsigned long long d;
    asm("add.rn.f32x2 %0, %1, %2;" : "=l"(d) : "l"(a), "l"(b));
    return d;
}
static __device__ __forceinline__ float hadd2(unsigned long long v) {
    float lo, hi;
    asm("mov.b64 {%0,%1}, %2;" : "=f"(lo), "=f"(hi) : "l"(v));
    return lo + hi;
}
static __device__ __forceinline__ float lo2(unsigned long long v) {
    float lo, hi;
    asm("mov.b64 {%0,%1}, %2;" : "=f"(lo), "=f"(hi) : "l"(v));
    return lo;
}
static __device__ __forceinline__ void lds16(
    unsigned long long& x, unsigned long long& y, unsigned int addr) {
    asm volatile("ld.shared.v2.u64 {%0,%1}, [%2];" : "=l"(x), "=l"(y) : "r"(addr));
}
static __device__ __forceinline__ float frcp(float x) {
    float r; asm("rcp.approx.f32 %0, %1;" : "=f"(r) : "f"(x)); return r;
}

// ---------------------------------------------------------------------------
// Rank prologue: counting rank by (length desc, index asc). Deterministic.
// ---------------------------------------------------------------------------
__global__ __launch_bounds__(BATCH) void crf_rank_kernel(
    const int* __restrict__ lengths)
{
    __shared__ int sl[BATCH];
    const int i = threadIdx.x;
    sl[i] = lengths[i];
    __syncthreads();
    const int Li = sl[i];
    int r = 0;
    for (int j = 0; j < BATCH; ++j) {
        const int Lj = sl[j];
        r += (Lj > Li) || (Lj == Li && j < i);
    }
    g_perm[r] = i;
}

// 36-fma2 dot. Class A = lane (24 row-pairs) + half-share of class
// B = 32+(lane>>1) (12 row-pairs, parity-split, joined via one shfl_xor).
// R9: the B-side operands are register SELECTS of the already-loaded A/C
// halves (par ? xC : xA) instead of a third LDS — smem ops/step 20 -> 14;
// bit-identical math (the addresses were exact duplicates).
#define CRF_DOT36(sb, parq, TA, TB, dotA, dotB, rfirst)                       \
    {                                                                         \
        unsigned long long cA0=0ull,cA1=0ull,cA2=0ull,cA3=0ull;               \
        unsigned long long cB0=0ull,cB1=0ull;                                 \
        unsigned long long e_first=0ull;                                      \
        _Pragma("unroll")                                                     \
        for (int m = 0; m < 6; ++m) {                                         \
            unsigned long long xA0,xA1,xC0,xC1;                               \
            lds16(xA0, xA1, (sb) + 16u * m);                                  \
            lds16(xC0, xC1, (sb) + 16u * m + 96u);                            \
            if (m == 0) e_first = xA0;                                        \
            const unsigned long long xb0 = (parq) ? xC0 : xA0;                \
            const unsigned long long xb1 = (parq) ? xC1 : xA1;                \
            cA0 = fma2(xA0, TA[4*m+0], cA0);                                  \
            cA1 = fma2(xA1, TA[4*m+1], cA1);                                  \
            cA2 = fma2(xC0, TA[4*m+2], cA2);                                  \
            cA3 = fma2(xC1, TA[4*m+3], cA3);                                  \
            cB0 = fma2(xb0, TB[2*m+0], cB0);                                  \
            cB1 = fma2(xb1, TB[2*m+1], cB1);                                  \
        }                                                                     \
        rfirst = lo2(e_first);                                                \
        dotA = hadd2(add2(add2(cA0, cA1), add2(cA2, cA3)));                   \
        float _pb = hadd2(add2(cB0, cB1));                                    \
        dotB = _pb + __shfl_xor_sync(FULL, _pb, 1);                           \
    }

// ---------------------------------------------------------------------------
// Meet-in-the-middle CRF with length-aware scheduling.
// Block k owns length-ranks {k, k+128, k+256, k+384} (slots 0..3).
// Warp->(slot, role) pairs LONG half-chains with SHORT ones per SMSP:
//   w0:(0,F) w1:(0,B) w2:(1,F) w3:(1,B)
//   w4:(3,B) w5:(3,F) w6:(2,B) w7:(2,F)
// ---------------------------------------------------------------------------
__global__ __launch_bounds__(256, 1) void crf_mitm_kernel(
    const float* __restrict__ scores,
    const int*   __restrict__ target,
    const int*   __restrict__ lengths,
    const float* __restrict__ trans,
    float*       __restrict__ out)
{
    __shared__ float sh_ex[8][2][64];  // per-warp ping-pong exchange buffers
    __shared__ float sh_v[4][48];      // backward result vectors (per slot)
    __shared__ float sh_mb[4];         // backward Mlog
    __shared__ float sh_xb[4];         // backward X partial

    const int wid  = threadIdx.x >> 5;
    const int lane = threadIdx.x & 31;

    const int  slot  = (wid < 4) ? (wid >> 1) : (3 - ((wid - 4) >> 1));
    const bool isfwd = !((wid & 1) ^ ((wid >> 2) & 1));
    const int  b     = g_perm[blockIdx.x + 128 * slot];

    const int L = lengths[b];
    const int h = (L >= 2) ? (L >> 1) : 1;

    const int  cA  = lane;
    const int  cB  = 32 + (lane >> 1);
    const int  par = lane & 1;

    const float* spA = scores + (size_t)b * NC + cA;
    const float* spB = scores + (size_t)b * NC + cB;
    const size_t rs  = (size_t)BATCH * NC;

    unsigned int shbase[2];
    shbase[0] = (unsigned int)__cvta_generic_to_shared(&sh_ex[wid][0][0]);
    shbase[1] = (unsigned int)__cvta_generic_to_shared(&sh_ex[wid][1][0]);

    float aA = 0.f, aB = 0.f, Mf = 0.f, Xpart = 0.f;

    if (isfwd) {
        // ===================== FORWARD role =================================
        for (int t = lane; t < h; t += 32) {
            const int tgt = target[t * BATCH + b];
            float v = scores[((size_t)t * BATCH + b) * NC + tgt];
            if (t > 0) v += trans[target[(t - 1) * BATCH + b] * NC + tgt];
            Xpart += v;
        }
#pragma unroll
        for (int o = 16; o > 0; o >>= 1)
            Xpart += __shfl_xor_sync(FULL, Xpart, o);

        unsigned long long TA[24], TB[12];
#pragma unroll
        for (int m = 0; m < 6; ++m) {
            int q;
            q = 2*m;      TA[4*m+0] = pk2(__expf(trans[(2*q)*NC + cA]), __expf(trans[(2*q+1)*NC + cA]));
            q = 2*m+1;    TA[4*m+1] = pk2(__expf(trans[(2*q)*NC + cA]), __expf(trans[(2*q+1)*NC + cA]));
            q = 2*m+12;   TA[4*m+2] = pk2(__expf(trans[(2*q)*NC + cA]), __expf(trans[(2*q+1)*NC + cA]));
            q = 2*m+13;   TA[4*m+3] = pk2(__expf(trans[(2*q)*NC + cA]), __expf(trans[(2*q+1)*NC + cA]));
        }
#pragma unroll
        for (int j = 0; j < 12; ++j) {
            const int q = j + 12 * par;
            TB[j] = pk2(__expf(trans[(2*q)*NC + cB]), __expf(trans[(2*q+1)*NC + cB]));
        }

        aA = __expf(spA[0]);
        aB = __expf(spB[0]);

        float pA[4], pB[4];
#pragma unroll
        for (int k = 0; k < 4; ++k) {
            pA[k] = spA[(size_t)(1 + k) * rs];
            pB[k] = spB[(size_t)(1 + k) * rs];
        }

#define FWD_STEP(T, SLOT)                                                     \
    {                                                                         \
        const float sA = pA[SLOT];                                            \
        const float sB = pB[SLOT];                                            \
        pA[SLOT] = spA[(size_t)((T) + 4) * rs];                               \
        pB[SLOT] = spB[(size_t)((T) + 4) * rs];                               \
        const float wA = __expf(sA);                                          \
        const float wB = __expf(sB);                                          \
        {                                                                     \
            float* shp = &sh_ex[wid][(SLOT) & 1][0];                          \
            shp[lane] = aA;                                                   \
            if (!par) shp[cB] = aB;                                           \
        }                                                                     \
        __syncwarp();                                                         \
        float dotA, dotB, r;                                                  \
        CRF_DOT36(shbase[(SLOT) & 1], par, TA, TB, dotA, dotB, r)             \
        const float inv = frcp(r);                                            \
        Mf += __logf(r);                                                      \
        aA = dotA * (wA * inv);                                               \
        aB = dotB * (wB * inv);                                               \
    }

        int t = 1;
        for (; t + 3 < h; t += 4) {
            FWD_STEP(t,     0)
            FWD_STEP(t + 1, 1)
            FWD_STEP(t + 2, 2)
            FWD_STEP(t + 3, 3)
        }
        for (; t < h; ++t) {
            const float sA = spA[(size_t)t * rs];
            const float sB = spB[(size_t)t * rs];
            const float wA = __expf(sA);
            const float wB = __expf(sB);
            {
                float* shp = &sh_ex[wid][(t - 1) & 1][0];
                shp[lane] = aA;
                if (!par) shp[cB] = aB;
            }
            __syncwarp();
            float dotA, dotB, r;
            CRF_DOT36(shbase[(t - 1) & 1], par, TA, TB, dotA, dotB, r)
            const float inv = frcp(r);
            Mf += __logf(r);
            aA = dotA * (wA * inv);
            aB = dotB * (wB * inv);
        }
#undef FWD_STEP
    } else {
        // ===================== BACKWARD role ================================
        float Xb = 0.0f;
        for (int t = h + lane; t < L; t += 32) {
            const int tgt = target[t * BATCH + b];
            float v = scores[((size_t)t * BATCH + b) * NC + tgt]
                    + trans[target[(t - 1) * BATCH + b] * NC + tgt];
            Xb += v;
        }
#pragma unroll
        for (int o = 16; o > 0; o >>= 1)
            Xb += __shfl_xor_sync(FULL, Xb, o);

        unsigned long long TA[24], TB[12];
#pragma unroll
        for (int m = 0; m < 6; ++m) {
            int q;
            q = 2*m;      TA[4*m+0] = pk2(__expf(trans[cA*NC + 2*q]), __expf(trans[cA*NC + 2*q+1]));
            q = 2*m+1;    TA[4*m+1] = pk2(__expf(trans[cA*NC + 2*q]), __expf(trans[cA*NC + 2*q+1]));
            q = 2*m+12;   TA[4*m+2] = pk2(__expf(trans[cA*NC + 2*q]), __expf(trans[cA*NC + 2*q+1]));
            q = 2*m+13;   TA[4*m+3] = pk2(__expf(trans[cA*NC + 2*q]), __expf(trans[cA*NC + 2*q+1]));
        }
#pragma unroll
        for (int j = 0; j < 12; ++j) {
            const int q = j + 12 * par;
            TB[j] = pk2(__expf(trans[cB*NC + 2*q]), __expf(trans[cB*NC + 2*q+1]));
        }

        float Mb = 0.0f;
        float xA = 1.0f, xB = 1.0f;
        const int nsteps = L - h;

        if (nsteps > 0) {
            float gA = __expf(spA[(size_t)(L - 1) * rs]);
            float gB = __expf(spB[(size_t)(L - 1) * rs]);

            float qA[4], qB[4];
#pragma unroll
            for (int k = 0; k < 4; ++k) {
                int tt = L - 2 - k; if (tt < 0) tt = 0;
                qA[k] = spA[(size_t)tt * rs];
                qB[k] = spB[(size_t)tt * rs];
            }

#define BWD_STEP(T, SLOT)                                                     \
    {                                                                         \
        const float sA = qA[SLOT];                                            \
        const float sB = qB[SLOT];                                            \
        qA[SLOT] = spA[(size_t)((T) - 5) * rs];                               \
        qB[SLOT] = spB[(size_t)((T) - 5) * rs];                               \
        const float wA = __expf(sA);                                          \
        const float wB = __expf(sB);                                          \
        {                                                                     \
            float* shp = &sh_ex[wid][(SLOT) & 1][0];                          \
            shp[lane] = gA;                                                   \
            if (!par) shp[cB] = gB;                                           \
        }                                                                     \
        __syncwarp();                                                         \
        float dotA, dotB, r;                                                  \
        CRF_DOT36(shbase[(SLOT) & 1], par, TA, TB, dotA, dotB, r)             \
        const float inv = frcp(r);                                            \
        Mb += __logf(r);                                                      \
        xA = dotA * inv;                                                      \
        xB = dotB * inv;                                                      \
        gA = xA * wA;                                                         \
        gB = xB * wB;                                                         \
    }

            int t = L - 1;
            for (; t - 3 >= h && t >= 8; t -= 4) {
                BWD_STEP(t,     0)
                BWD_STEP(t - 1, 1)
                BWD_STEP(t - 2, 2)
                BWD_STEP(t - 3, 3)
            }
            for (; t >= h; --t) {
                int tm = t - 1; if (tm < 0) tm = 0;
                const float sA = spA[(size_t)tm * rs];
                const float sB = spB[(size_t)tm * rs];
                const float wA = __expf(sA);
                const float wB = __expf(sB);
                const int buf = (L - 1 - t) & 1;
                {
                    float* shp = &sh_ex[wid][buf][0];
                    shp[lane] = gA;
                    if (!par) shp[cB] = gB;
                }
                __syncwarp();
                float dotA, dotB, r;
                CRF_DOT36(shbase[buf], par, TA, TB, dotA, dotB, r)
                const float inv = frcp(r);
                Mb += __logf(r);
                xA = dotA * inv;
                xB = dotB * inv;
                gA = xA * wA;
                gB = xB * wB;
            }
#undef BWD_STEP
        }

        sh_v[slot][lane] = xA;
        if (!par) sh_v[slot][cB] = xB;
        if (lane == 0) { sh_mb[slot] = Mb; sh_xb[slot] = Xb; }
    }

    __syncthreads();

    if (isfwd) {
        // u[32+lane] lives as aB on lane 2*lane (valid for lane < 16)
        const float u32 = __shfl_sync(FULL, aB, (lane << 1) & 31);
        float prod = aA * sh_v[slot][lane];
        if (lane < 16) prod += u32 * sh_v[slot][32 + lane];
#pragma unroll
        for (int o = 16; o > 0; o >>= 1)
            prod += __shfl_xor_sync(FULL, prod, o);
        if (lane == 0) {
            const float X    = Xpart + sh_xb[slot];
            const float logZ = Mf + sh_mb[slot] + __logf(prod);
            out[b]         = X;
            out[BATCH + b] = X - logZ;
        }
    }
}

// ---------------------------------------------------------------------------
extern "C" void kernel_launch(void* const* d_in, const int* in_sizes, int n_in,
                              void* d_out, int out_size)
{
    const float* scores  = (const float*)d_in[0];  // (1024, 512, 48) f32
    const int*   target  = (const int*)  d_in[1];  // (1024, 512) i32
    const int*   lengths = (const int*)  d_in[2];  // (512,) i32
    const float* trans   = (const float*)d_in[3];  // (48, 48) f32
    float* out = (float*)d_out;                    // (2, 512) f32

    crf_rank_kernel<<<1, BATCH>>>(lengths);
    crf_mitm_kernel<<<BATCH / 4, 256>>>(scores, target, lengths, trans, out);
}

// round 10
// speedup vs baseline: 1.2892x; 1.2892x over previous
#include <cuda_runtime.h>

#define SEQ   1024
#define BATCH 512
#define NC    48
#define FULL  0xffffffffu

__device__ int g_perm[BATCH];   // rank r -> batch index (descending length)

// ---- packed f32x2 helpers (sm_103a) ------------------------------------
static __device__ __forceinline__ unsigned long long pk2(float lo, float hi) {
    unsigned long long r;
    asm("mov.b64 %0, {%1,%2};" : "=l"(r) : "f"(lo), "f"(hi));
    return r;
}
static __device__ __forceinline__ unsigned long long fma2(
    unsigned long long a, unsigned long long b, unsigned long long c) {
    unsigned long long d;
    asm("fma.rn.f32x2 %0, %1, %2, %3;" : "=l"(d) : "l"(a), "l"(b), "l"(c));
    return d;
}
static __device__ __forceinline__ unsigned long long add2(
    unsigned long long a, unsigned long long b) {
    unsigned long long d;
    asm("add.rn.f32x2 %0, %1, %2;" : "=l"(d) : "l"(a), "l"(b));
    return d;
}
static __device__ __forceinline__ float hadd2(unsigned long long v) {
    float lo, hi;
    asm("mov.b64 {%0,%1}, %2;" : "=f"(lo), "=f"(hi) : "l"(v));
    return lo + hi;
}
static __device__ __forceinline__ float lo2(unsigned long long v) {
    float lo, hi;
    asm("mov.b64 {%0,%1}, %2;" : "=f"(lo), "=f"(hi) : "l"(v));
    return lo;
}
static __device__ __forceinline__ void lds16(
    unsigned long long& x, unsigned long long& y, unsigned int addr) {
    asm volatile("ld.shared.v2.u64 {%0,%1}, [%2];" : "=l"(x), "=l"(y) : "r"(addr));
}
static __device__ __forceinline__ float frcp(float x) {
    float r; asm("rcp.approx.f32 %0, %1;" : "=f"(r) : "f"(x)); return r;
}

// ---------------------------------------------------------------------------
// Rank prologue: counting rank by (length desc, index asc). Deterministic.
// ---------------------------------------------------------------------------
__global__ __launch_bounds__(BATCH) void crf_rank_kernel(
    const int* __restrict__ lengths)
{
    __shared__ int sl[BATCH];
    const int i = threadIdx.x;
    sl[i] = lengths[i];
    __syncthreads();
    const int Li = sl[i];
    int r = 0;
    for (int j = 0; j < BATCH; ++j) {
        const int Lj = sl[j];
        r += (Lj > Li) || (Lj == Li && j < i);
    }
    g_perm[r] = i;
}

// 36-fma2 dot (R8 version — the fastest measured). Class A = lane (24
// row-pairs) + half-share of class B = 32+(lane>>1) (12 row-pairs,
// parity-split via a third per-parity LDS, joined with one shfl_xor).
#define CRF_DOT36(sb, boff, TA, TB, dotA, dotB, rfirst)                       \
    {                                                                         \
        unsigned long long cA0=0ull,cA1=0ull,cA2=0ull,cA3=0ull;               \
        unsigned long long cB0=0ull,cB1=0ull;                                 \
        unsigned long long e_first=0ull;                                      \
        _Pragma("unroll")                                                     \
        for (int m = 0; m < 6; ++m) {                                         \
            unsigned long long xA0,xA1,xC0,xC1,xB0,xB1;                       \
            lds16(xA0, xA1, (sb) + 16u * m);                                  \
            lds16(xC0, xC1, (sb) + 16u * m + 96u);                            \
            lds16(xB0, xB1, (sb) + 16u * m + (boff));                         \
            if (m == 0) e_first = xA0;                                        \
            cA0 = fma2(xA0, TA[4*m+0], cA0);                                  \
            cA1 = fma2(xA1, TA[4*m+1], cA1);                                  \
            cA2 = fma2(xC0, TA[4*m+2], cA2);                                  \
            cA3 = fma2(xC1, TA[4*m+3], cA3);                                  \
            cB0 = fma2(xB0, TB[2*m+0], cB0);                                  \
            cB1 = fma2(xB1, TB[2*m+1], cB1);                                  \
        }                                                                     \
        rfirst = lo2(e_first);                                                \
        dotA = hadd2(add2(add2(cA0, cA1), add2(cA2, cA3)));                   \
        float _pb = hadd2(add2(cB0, cB1));                                    \
        dotB = _pb + __shfl_xor_sync(FULL, _pb, 1);                           \
    }

// ---------------------------------------------------------------------------
// Meet-in-the-middle CRF with contention-shaped scheduling.
// Block k owns length-ranks {k, 255-k, 256+k, 511-k} (slots 0..3):
//   - per-block length sum is ~constant (perfect per-SM balance), and
//   - with the SMSP pairing below, the longest chain (slot 0) shares its
//     scheduler with the SHORTEST (slot 3), which retires almost at once.
// Warp->(slot, role):  w0:(0,F) w1:(0,B) w2:(1,F) w3:(1,B)
//                      w4:(3,B) w5:(3,F) w6:(2,B) w7:(2,F)
// (SMSP = wid&3: SMSP0 = fwd(slot0)+bwd(slot3), SMSP1 = bwd(slot0)+fwd(slot3),
//  SMSP2 = fwd(slot1)+bwd(slot2), SMSP3 = bwd(slot1)+fwd(slot2).)
// ---------------------------------------------------------------------------
__global__ __launch_bounds__(256, 1) void crf_mitm_kernel(
    const float* __restrict__ scores,
    const int*   __restrict__ target,
    const int*   __restrict__ lengths,
    const float* __restrict__ trans,
    float*       __restrict__ out)
{
    __shared__ float sh_ex[8][2][64];  // per-warp ping-pong exchange buffers
    __shared__ float sh_v[4][48];      // backward result vectors (per slot)
    __shared__ float sh_mb[4];         // backward Mlog
    __shared__ float sh_xb[4];         // backward X partial

    const int wid  = threadIdx.x >> 5;
    const int lane = threadIdx.x & 31;

    const int  slot  = (wid < 4) ? (wid >> 1) : (3 - ((wid - 4) >> 1));
    const bool isfwd = !((wid & 1) ^ ((wid >> 2) & 1));

    const int k    = blockIdx.x;
    const int rank = (slot == 0) ? k
                   : (slot == 1) ? (255 - k)
                   : (slot == 2) ? (256 + k)
                   :               (511 - k);
    const int b    = g_perm[rank];

    const int L = lengths[b];
    const int h = (L >= 2) ? (L >> 1) : 1;

    const int  cA  = lane;
    const int  cB  = 32 + (lane >> 1);
    const int  par = lane & 1;
    const unsigned int boff = 96u * (unsigned)par;

    const float* spA = scores + (size_t)b * NC + cA;
    const float* spB = scores + (size_t)b * NC + cB;
    const size_t rs  = (size_t)BATCH * NC;

    unsigned int shbase[2];
    shbase[0] = (unsigned int)__cvta_generic_to_shared(&sh_ex[wid][0][0]);
    shbase[1] = (unsigned int)__cvta_generic_to_shared(&sh_ex[wid][1][0]);

    float aA = 0.f, aB = 0.f, Mf = 0.f, Xpart = 0.f;

    if (isfwd) {
        // ===================== FORWARD role =================================
        for (int t = lane; t < h; t += 32) {
            const int tgt = target[t * BATCH + b];
            float v = scores[((size_t)t * BATCH + b) * NC + tgt];
            if (t > 0) v += trans[target[(t - 1) * BATCH + b] * NC + tgt];
            Xpart += v;
        }
#pragma unroll
        for (int o = 16; o > 0; o >>= 1)
            Xpart += __shfl_xor_sync(FULL, Xpart, o);

        unsigned long long TA[24], TB[12];
#pragma unroll
        for (int m = 0; m < 6; ++m) {
            int q;
            q = 2*m;      TA[4*m+0] = pk2(__expf(trans[(2*q)*NC + cA]), __expf(trans[(2*q+1)*NC + cA]));
            q = 2*m+1;    TA[4*m+1] = pk2(__expf(trans[(2*q)*NC + cA]), __expf(trans[(2*q+1)*NC + cA]));
            q = 2*m+12;   TA[4*m+2] = pk2(__expf(trans[(2*q)*NC + cA]), __expf(trans[(2*q+1)*NC + cA]));
            q = 2*m+13;   TA[4*m+3] = pk2(__expf(trans[(2*q)*NC + cA]), __expf(trans[(2*q+1)*NC + cA]));
        }
#pragma unroll
        for (int j = 0; j < 12; ++j) {
            const int q = j + 12 * par;
            TB[j] = pk2(__expf(trans[(2*q)*NC + cB]), __expf(trans[(2*q+1)*NC + cB]));
        }

        aA = __expf(spA[0]);
        aB = __expf(spB[0]);

        float pA[4], pB[4];
#pragma unroll
        for (int kk = 0; kk < 4; ++kk) {
            pA[kk] = spA[(size_t)(1 + kk) * rs];
            pB[kk] = spB[(size_t)(1 + kk) * rs];
        }

#define FWD_STEP(T, SLOT)                                                     \
    {                                                                         \
        const float sA = pA[SLOT];                                            \
        const float sB = pB[SLOT];                                            \
        pA[SLOT] = spA[(size_t)((T) + 4) * rs];                               \
        pB[SLOT] = spB[(size_t)((T) + 4) * rs];                               \
        const float wA = __expf(sA);                                          \
        const float wB = __expf(sB);                                          \
        {                                                                     \
            float* shp = &sh_ex[wid][(SLOT) & 1][0];                          \
            shp[lane] = aA;                                                   \
            if (!par) shp[cB] = aB;                                           \
        }                                                                     \
        __syncwarp();                                                         \
        float dotA, dotB, r;                                                  \
        CRF_DOT36(shbase[(SLOT) & 1], boff, TA, TB, dotA, dotB, r)            \
        const float inv = frcp(r);                                            \
        Mf += __logf(r);                                                      \
        aA = dotA * (wA * inv);                                               \
        aB = dotB * (wB * inv);                                               \
    }

        int t = 1;
        for (; t + 3 < h; t += 4) {
            FWD_STEP(t,     0)
            FWD_STEP(t + 1, 1)
            FWD_STEP(t + 2, 2)
            FWD_STEP(t + 3, 3)
        }
        for (; t < h; ++t) {
            const float sA = spA[(size_t)t * rs];
            const float sB = spB[(size_t)t * rs];
            const float wA = __expf(sA);
            const float wB = __expf(sB);
            {
                float* shp = &sh_ex[wid][(t - 1) & 1][0];
                shp[lane] = aA;
                if (!par) shp[cB] = aB;
            }
            __syncwarp();
            float dotA, dotB, r;
            CRF_DOT36(shbase[(t - 1) & 1], boff, TA, TB, dotA, dotB, r)
            const float inv = frcp(r);
            Mf += __logf(r);
            aA = dotA * (wA * inv);
            aB = dotB * (wB * inv);
        }
#undef FWD_STEP
    } else {
        // ===================== BACKWARD role ================================
        float Xb = 0.0f;
        for (int t = h + lane; t < L; t += 32) {
            const int tgt = target[t * BATCH + b];
            float v = scores[((size_t)t * BATCH + b) * NC + tgt]
                    + trans[target[(t - 1) * BATCH + b] * NC + tgt];
            Xb += v;
        }
#pragma unroll
        for (int o = 16; o > 0; o >>= 1)
            Xb += __shfl_xor_sync(FULL, Xb, o);

        unsigned long long TA[24], TB[12];
#pragma unroll
        for (int m = 0; m < 6; ++m) {
            int q;
            q = 2*m;      TA[4*m+0] = pk2(__expf(trans[cA*NC + 2*q]), __expf(trans[cA*NC + 2*q+1]));
            q = 2*m+1;    TA[4*m+1] = pk2(__expf(trans[cA*NC + 2*q]), __expf(trans[cA*NC + 2*q+1]));
            q = 2*m+12;   TA[4*m+2] = pk2(__expf(trans[cA*NC + 2*q]), __expf(trans[cA*NC + 2*q+1]));
            q = 2*m+13;   TA[4*m+3] = pk2(__expf(trans[cA*NC + 2*q]), __expf(trans[cA*NC + 2*q+1]));
        }
#pragma unroll
        for (int j = 0; j < 12; ++j) {
            const int q = j + 12 * par;
            TB[j] = pk2(__expf(trans[cB*NC + 2*q]), __expf(trans[cB*NC + 2*q+1]));
        }

        float Mb = 0.0f;
        float xA = 1.0f, xB = 1.0f;
        const int nsteps = L - h;

        if (nsteps > 0) {
            float gA = __expf(spA[(size_t)(L - 1) * rs]);
            float gB = __expf(spB[(size_t)(L - 1) * rs]);

            float qA[4], qB[4];
#pragma unroll
            for (int kk = 0; kk < 4; ++kk) {
                int tt = L - 2 - kk; if (tt < 0) tt = 0;
                qA[kk] = spA[(size_t)tt * rs];
                qB[kk] = spB[(size_t)tt * rs];
            }

#define BWD_STEP(T, SLOT)                                                     \
    {                                                                         \
        const float sA = qA[SLOT];                                            \
        const float sB = qB[SLOT];                                            \
        qA[SLOT] = spA[(size_t)((T) - 5) * rs];                               \
        qB[SLOT] = spB[(size_t)((T) - 5) * rs];                               \
        const float wA = __expf(sA);                                          \
        const float wB = __expf(sB);                                          \
        {                                                                     \
            float* shp = &sh_ex[wid][(SLOT) & 1][0];                          \
            shp[lane] = gA;                                                   \
            if (!par) shp[cB] = gB;                                           \
        }                                                                     \
        __syncwarp();                                                         \
        float dotA, dotB, r;                                                  \
        CRF_DOT36(shbase[(SLOT) & 1], boff, TA, TB, dotA, dotB, r)            \
        const float inv = frcp(r);                                            \
        Mb += __logf(r);                                                      \
        xA = dotA * inv;                                                      \
        xB = dotB * inv;                                                      \
        gA = xA * wA;                                                         \
        gB = xB * wB;                                                         \
    }

            int t = L - 1;
            for (; t - 3 >= h && t >= 8; t -= 4) {
                BWD_STEP(t,     0)
                BWD_STEP(t - 1, 1)
                BWD_STEP(t - 2, 2)
                BWD_STEP(t - 3, 3)
            }
            for (; t >= h; --t) {
                int tm = t - 1; if (tm < 0) tm = 0;
                const float sA = spA[(size_t)tm * rs];
                const float sB = spB[(size_t)tm * rs];
                const float wA = __expf(sA);
                const float wB = __expf(sB);
                const int buf = (L - 1 - t) & 1;
                {
                    float* shp = &sh_ex[wid][buf][0];
                    shp[lane] = gA;
                    if (!par) shp[cB] = gB;
                }
                __syncwarp();
                float dotA, dotB, r;
                CRF_DOT36(shbase[buf], boff, TA, TB, dotA, dotB, r)
                const float inv = frcp(r);
                Mb += __logf(r);
                xA = dotA * inv;
                xB = dotB * inv;
                gA = xA * wA;
                gB = xB * wB;
            }
#undef BWD_STEP
        }

        sh_v[slot][lane] = xA;
        if (!par) sh_v[slot][cB] = xB;
        if (lane == 0) { sh_mb[slot] = Mb; sh_xb[slot] = Xb; }
    }

    __syncthreads();

    if (isfwd) {
        // u[32+lane] lives as aB on lane 2*lane (valid for lane < 16)
        const float u32 = __shfl_sync(FULL, aB, (lane << 1) & 31);
        float prod = aA * sh_v[slot][lane];
        if (lane < 16) prod += u32 * sh_v[slot][32 + lane];
#pragma unroll
        for (int o = 16; o > 0; o >>= 1)
            prod += __shfl_xor_sync(FULL, prod, o);
        if (lane == 0) {
            const float X    = Xpart + sh_xb[slot];
            const float logZ = Mf + sh_mb[slot] + __logf(prod);
            out[b]         = X;
            out[BATCH + b] = X - logZ;
        }
    }
}

// ---------------------------------------------------------------------------
extern "C" void kernel_launch(void* const* d_in, const int* in_sizes, int n_in,
                              void* d_out, int out_size)
{
    const float* scores  = (const float*)d_in[0];  // (1024, 512, 48) f32
    const int*   target  = (const int*)  d_in[1];  // (1024, 512) i32
    const int*   lengths = (const int*)  d_in[2];  // (512,) i32
    const float* trans   = (const float*)d_in[3];  // (48, 48) f32
    float* out = (float*)d_out;                    // (2, 512) f32

    crf_rank_kernel<<<1, BATCH>>>(lengths);
    crf_mitm_kernel<<<BATCH / 4, 256>>>(scores, target, lengths, trans, out);
}

// round 11
// speedup vs baseline: 1.3220x; 1.0254x over previous
#include <cuda_runtime.h>

#define SEQ   1024
#define BATCH 512
#define NC    48
#define FULL  0xffffffffu

__device__ int g_perm[BATCH];   // rank r -> batch index (descending length)

// ---- packed f32x2 helpers (sm_103a) ------------------------------------
static __device__ __forceinline__ unsigned long long pk2(float lo, float hi) {
    unsigned long long r;
    asm("mov.b64 %0, {%1,%2};" : "=l"(r) : "f"(lo), "f"(hi));
    return r;
}
static __device__ __forceinline__ unsigned long long fma2(
    unsigned long long a, unsigned long long b, unsigned long long c) {
    unsigned long long d;
    asm("fma.rn.f32x2 %0, %1, %2, %3;" : "=l"(d) : "l"(a), "l"(b), "l"(c));
    return d;
}
static __device__ __forceinline__ unsigned long long add2(
    unsigned long long a, unsigned long long b) {
    unsigned long long d;
    asm("add.rn.f32x2 %0, %1, %2;" : "=l"(d) : "l"(a), "l"(b));
    return d;
}
static __device__ __forceinline__ float hadd2(unsigned long long v) {
    float lo, hi;
    asm("mov.b64 {%0,%1}, %2;" : "=f"(lo), "=f"(hi) : "l"(v));
    return lo + hi;
}
static __device__ __forceinline__ float lo2(unsigned long long v) {
    float lo, hi;
    asm("mov.b64 {%0,%1}, %2;" : "=f"(lo), "=f"(hi) : "l"(v));
    return lo;
}
static __device__ __forceinline__ void lds16(
    unsigned long long& x, unsigned long long& y, unsigned int addr) {
    asm volatile("ld.shared.v2.u64 {%0,%1}, [%2];" : "=l"(x), "=l"(y) : "r"(addr));
}
static __device__ __forceinline__ float frcp(float x) {
    float r; asm("rcp.approx.f32 %0, %1;" : "=f"(r) : "f"(x)); return r;
}

// ---------------------------------------------------------------------------
// Rank prologue: counting rank by (length desc, index asc). Deterministic.
// ---------------------------------------------------------------------------
__global__ __launch_bounds__(BATCH) void crf_rank_kernel(
    const int* __restrict__ lengths)
{
    __shared__ int sl[BATCH];
    const int i = threadIdx.x;
    sl[i] = lengths[i];
    __syncthreads();
    const int Li = sl[i];
    int r = 0;
    for (int j = 0; j < BATCH; ++j) {
        const int Lj = sl[j];
        r += (Lj > Li) || (Lj == Li && j < i);
    }
    g_perm[r] = i;
}

// 36-fma2 dot (R8 version — the fastest measured). Class A = lane (24
// row-pairs) + half-share of class B = 32+(lane>>1) (12 row-pairs,
// parity-split via a third per-parity LDS, joined with one shfl_xor).
#define CRF_DOT36(sb, boff, TA, TB, dotA, dotB, rfirst)                       \
    {                                                                         \
        unsigned long long cA0=0ull,cA1=0ull,cA2=0ull,cA3=0ull;               \
        unsigned long long cB0=0ull,cB1=0ull;                                 \
        unsigned long long e_first=0ull;                                      \
        _Pragma("unroll")                                                     \
        for (int m = 0; m < 6; ++m) {                                         \
            unsigned long long xA0,xA1,xC0,xC1,xB0,xB1;                       \
            lds16(xA0, xA1, (sb) + 16u * m);                                  \
            lds16(xC0, xC1, (sb) + 16u * m + 96u);                            \
            lds16(xB0, xB1, (sb) + 16u * m + (boff));                         \
            if (m == 0) e_first = xA0;                                        \
            cA0 = fma2(xA0, TA[4*m+0], cA0);                                  \
            cA1 = fma2(xA1, TA[4*m+1], cA1);                                  \
            cA2 = fma2(xC0, TA[4*m+2], cA2);                                  \
            cA3 = fma2(xC1, TA[4*m+3], cA3);                                  \
            cB0 = fma2(xB0, TB[2*m+0], cB0);                                  \
            cB1 = fma2(xB1, TB[2*m+1], cB1);                                  \
        }                                                                     \
        rfirst = lo2(e_first);                                                \
        dotA = hadd2(add2(add2(cA0, cA1), add2(cA2, cA3)));                   \
        float _pb = hadd2(add2(cB0, cB1));                                    \
        dotB = _pb + __shfl_xor_sync(FULL, _pb, 1);                           \
    }

// ---------------------------------------------------------------------------
// Meet-in-the-middle CRF, contention-optimal partition:
// block k owns length-ranks {2k, 2k+1, 511-2k, 510-2k} (slots 0..3):
//   two LONG chains + two TINY chains per block. 4 chain warps (one per
//   SMSP) run at the ~270cyc latency floor (4x52 crossbar < 270), so the
//   second long chain is FREE; the tiny partners retire almost at once.
// Warp->(slot, role):  w0:(0,F) w1:(0,B) w2:(1,F) w3:(1,B)
//                      w4:(3,B) w5:(3,F) w6:(2,B) w7:(2,F)
// (SMSP = wid&3: each SMSP gets one LONG warp + one TINY warp.)
// ---------------------------------------------------------------------------
__global__ __launch_bounds__(256, 1) void crf_mitm_kernel(
    const float* __restrict__ scores,
    const int*   __restrict__ target,
    const int*   __restrict__ lengths,
    const float* __restrict__ trans,
    float*       __restrict__ out)
{
    __shared__ float sh_ex[8][2][64];  // per-warp ping-pong exchange buffers
    __shared__ float sh_v[4][48];      // backward result vectors (per slot)
    __shared__ float sh_mb[4];         // backward Mlog
    __shared__ float sh_xb[4];         // backward X partial

    const int wid  = threadIdx.x >> 5;
    const int lane = threadIdx.x & 31;

    const int  slot  = (wid < 4) ? (wid >> 1) : (3 - ((wid - 4) >> 1));
    const bool isfwd = !((wid & 1) ^ ((wid >> 2) & 1));

    const int k    = blockIdx.x;
    const int rank = (slot == 0) ? (2 * k)
                   : (slot == 1) ? (2 * k + 1)
                   : (slot == 2) ? (511 - 2 * k)
                   :               (510 - 2 * k);
    const int b    = g_perm[rank];

    const int L = lengths[b];
    const int h = (L >= 2) ? (L >> 1) : 1;

    const int  cA  = lane;
    const int  cB  = 32 + (lane >> 1);
    const int  par = lane & 1;
    const unsigned int boff = 96u * (unsigned)par;

    const float* spA = scores + (size_t)b * NC + cA;
    const float* spB = scores + (size_t)b * NC + cB;
    const size_t rs  = (size_t)BATCH * NC;

    unsigned int shbase[2];
    shbase[0] = (unsigned int)__cvta_generic_to_shared(&sh_ex[wid][0][0]);
    shbase[1] = (unsigned int)__cvta_generic_to_shared(&sh_ex[wid][1][0]);

    float aA = 0.f, aB = 0.f, Mf = 0.f, Xpart = 0.f;

    if (isfwd) {
        // ===================== FORWARD role =================================
        for (int t = lane; t < h; t += 32) {
            const int tgt = target[t * BATCH + b];
            float v = scores[((size_t)t * BATCH + b) * NC + tgt];
            if (t > 0) v += trans[target[(t - 1) * BATCH + b] * NC + tgt];
            Xpart += v;
        }
#pragma unroll
        for (int o = 16; o > 0; o >>= 1)
            Xpart += __shfl_xor_sync(FULL, Xpart, o);

        unsigned long long TA[24], TB[12];
#pragma unroll
        for (int m = 0; m < 6; ++m) {
            int q;
            q = 2*m;      TA[4*m+0] = pk2(__expf(trans[(2*q)*NC + cA]), __expf(trans[(2*q+1)*NC + cA]));
            q = 2*m+1;    TA[4*m+1] = pk2(__expf(trans[(2*q)*NC + cA]), __expf(trans[(2*q+1)*NC + cA]));
            q = 2*m+12;   TA[4*m+2] = pk2(__expf(trans[(2*q)*NC + cA]), __expf(trans[(2*q+1)*NC + cA]));
            q = 2*m+13;   TA[4*m+3] = pk2(__expf(trans[(2*q)*NC + cA]), __expf(trans[(2*q+1)*NC + cA]));
        }
#pragma unroll
        for (int j = 0; j < 12; ++j) {
            const int q = j + 12 * par;
            TB[j] = pk2(__expf(trans[(2*q)*NC + cB]), __expf(trans[(2*q+1)*NC + cB]));
        }

        aA = __expf(spA[0]);
        aB = __expf(spB[0]);

        float pA[4], pB[4];
#pragma unroll
        for (int kk = 0; kk < 4; ++kk) {
            pA[kk] = spA[(size_t)(1 + kk) * rs];
            pB[kk] = spB[(size_t)(1 + kk) * rs];
        }

#define FWD_STEP(T, SLOT)                                                     \
    {                                                                         \
        const float sA = pA[SLOT];                                            \
        const float sB = pB[SLOT];                                            \
        pA[SLOT] = spA[(size_t)((T) + 4) * rs];                               \
        pB[SLOT] = spB[(size_t)((T) + 4) * rs];                               \
        const float wA = __expf(sA);                                          \
        const float wB = __expf(sB);                                          \
        {                                                                     \
            float* shp = &sh_ex[wid][(SLOT) & 1][0];                          \
            shp[lane] = aA;                                                   \
            if (!par) shp[cB] = aB;                                           \
        }                                                                     \
        __syncwarp();                                                         \
        float dotA, dotB, r;                                                  \
        CRF_DOT36(shbase[(SLOT) & 1], boff, TA, TB, dotA, dotB, r)            \
        const float inv = frcp(r);                                            \
        Mf += __logf(r);                                                      \
        aA = dotA * (wA * inv);                                               \
        aB = dotB * (wB * inv);                                               \
    }

        int t = 1;
        for (; t + 3 < h; t += 4) {
            FWD_STEP(t,     0)
            FWD_STEP(t + 1, 1)
            FWD_STEP(t + 2, 2)
            FWD_STEP(t + 3, 3)
        }
        for (; t < h; ++t) {
            const float sA = spA[(size_t)t * rs];
            const float sB = spB[(size_t)t * rs];
            const float wA = __expf(sA);
            const float wB = __expf(sB);
            {
                float* shp = &sh_ex[wid][(t - 1) & 1][0];
                shp[lane] = aA;
                if (!par) shp[cB] = aB;
            }
            __syncwarp();
            float dotA, dotB, r;
            CRF_DOT36(shbase[(t - 1) & 1], boff, TA, TB, dotA, dotB, r)
            const float inv = frcp(r);
            Mf += __logf(r);
            aA = dotA * (wA * inv);
            aB = dotB * (wB * inv);
        }
#undef FWD_STEP
    } else {
        // ===================== BACKWARD role ================================
        float Xb = 0.0f;
        for (int t = h + lane; t < L; t += 32) {
            const int tgt = target[t * BATCH + b];
            float v = scores[((size_t)t * BATCH + b) * NC + tgt]
                    + trans[target[(t - 1) * BATCH + b] * NC + tgt];
            Xb += v;
        }
#pragma unroll
        for (int o = 16; o > 0; o >>= 1)
            Xb += __shfl_xor_sync(FULL, Xb, o);

        unsigned long long TA[24], TB[12];
#pragma unroll
        for (int m = 0; m < 6; ++m) {
            int q;
            q = 2*m;      TA[4*m+0] = pk2(__expf(trans[cA*NC + 2*q]), __expf(trans[cA*NC + 2*q+1]));
            q = 2*m+1;    TA[4*m+1] = pk2(__expf(trans[cA*NC + 2*q]), __expf(trans[cA*NC + 2*q+1]));
            q = 2*m+12;   TA[4*m+2] = pk2(__expf(trans[cA*NC + 2*q]), __expf(trans[cA*NC + 2*q+1]));
            q = 2*m+13;   TA[4*m+3] = pk2(__expf(trans[cA*NC + 2*q]), __expf(trans[cA*NC + 2*q+1]));
        }
#pragma unroll
        for (int j = 0; j < 12; ++j) {
            const int q = j + 12 * par;
            TB[j] = pk2(__expf(trans[cB*NC + 2*q]), __expf(trans[cB*NC + 2*q+1]));
        }

        float Mb = 0.0f;
        float xA = 1.0f, xB = 1.0f;
        const int nsteps = L - h;

        if (nsteps > 0) {
            float gA = __expf(spA[(size_t)(L - 1) * rs]);
            float gB = __expf(spB[(size_t)(L - 1) * rs]);

            float qA[4], qB[4];
#pragma unroll
            for (int kk = 0; kk < 4; ++kk) {
                int tt = L - 2 - kk; if (tt < 0) tt = 0;
                qA[kk] = spA[(size_t)tt * rs];
                qB[kk] = spB[(size_t)tt * rs];
            }

#define BWD_STEP(T, SLOT)                                                     \
    {                                                                         \
        const float sA = qA[SLOT];                                            \
        const float sB = qB[SLOT];                                            \
        qA[SLOT] = spA[(size_t)((T) - 5) * rs];                               \
        qB[SLOT] = spB[(size_t)((T) - 5) * rs];                               \
        const float wA = __expf(sA);                                          \
        const float wB = __expf(sB);                                          \
        {                                                                     \
            float* shp = &sh_ex[wid][(SLOT) & 1][0];                          \
            shp[lane] = gA;                                                   \
            if (!par) shp[cB] = gB;                                           \
        }                                                                     \
        __syncwarp();                                                         \
        float dotA, dotB, r;                                                  \
        CRF_DOT36(shbase[(SLOT) & 1], boff, TA, TB, dotA, dotB, r)            \
        const float inv = frcp(r);                                            \
        Mb += __logf(r);                                                      \
        xA = dotA * inv;                                                      \
        xB = dotB * inv;                                                      \
        gA = xA * wA;                                                         \
        gB = xB * wB;                                                         \
    }

            int t = L - 1;
            for (; t - 3 >= h && t >= 8; t -= 4) {
                BWD_STEP(t,     0)
                BWD_STEP(t - 1, 1)
                BWD_STEP(t - 2, 2)
                BWD_STEP(t - 3, 3)
            }
            for (; t >= h; --t) {
                int tm = t - 1; if (tm < 0) tm = 0;
                const float sA = spA[(size_t)tm * rs];
                const float sB = spB[(size_t)tm * rs];
                const float wA = __expf(sA);
                const float wB = __expf(sB);
                const int buf = (L - 1 - t) & 1;
                {
                    float* shp = &sh_ex[wid][buf][0];
                    shp[lane] = gA;
                    if (!par) shp[cB] = gB;
                }
                __syncwarp();
                float dotA, dotB, r;
                CRF_DOT36(shbase[buf], boff, TA, TB, dotA, dotB, r)
                const float inv = frcp(r);
                Mb += __logf(r);
                xA = dotA * inv;
                xB = dotB * inv;
                gA = xA * wA;
                gB = xB * wB;
            }
#undef BWD_STEP
        }

        sh_v[slot][lane] = xA;
        if (!par) sh_v[slot][cB] = xB;
        if (lane == 0) { sh_mb[slot] = Mb; sh_xb[slot] = Xb; }
    }

    __syncthreads();

    if (isfwd) {
        // u[32+lane] lives as aB on lane 2*lane (valid for lane < 16)
        const float u32 = __shfl_sync(FULL, aB, (lane << 1) & 31);
        float prod = aA * sh_v[slot][lane];
        if (lane < 16) prod += u32 * sh_v[slot][32 + lane];
#pragma unroll
        for (int o = 16; o > 0; o >>= 1)
            prod += __shfl_xor_sync(FULL, prod, o);
        if (lane == 0) {
            const float X    = Xpart + sh_xb[slot];
            const float logZ = Mf + sh_mb[slot] + __logf(prod);
            out[b]         = X;
            out[BATCH + b] = X - logZ;
        }
    }
}

// ---------------------------------------------------------------------------
extern "C" void kernel_launch(void* const* d_in, const int* in_sizes, int n_in,
                              void* d_out, int out_size)
{
    const float* scores  = (const float*)d_in[0];  // (1024, 512, 48) f32
    const int*   target  = (const int*)  d_in[1];  // (1024, 512) i32
    const int*   lengths = (const int*)  d_in[2];  // (512,) i32
    const float* trans   = (const float*)d_in[3];  // (48, 48) f32
    float* out = (float*)d_out;                    // (2, 512) f32

    crf_rank_kernel<<<1, BATCH>>>(lengths);
    crf_mitm_kernel<<<BATCH / 4, 256>>>(scores, target, lengths, trans, out);
}